// round 7
// baseline (speedup 1.0000x reference)
#include <cuda_runtime.h>

#define B_   8
#define TE_  512
#define TD_  128
#define H_   256
#define ESPLIT 8

// Scratch (allocation-free rule: device globals)
__device__ float g_ep[B_ * TE_ * H_];      // enc @ W_a   [B,TE,H]
__device__ float g_dp[B_ * TD_ * H_];      // dec @ U_a   [B,TD,H]
__device__ float g_score[B_ * TD_ * TE_];  // raw scores -> weights (in place)
__device__ float g_part[ESPLIT][B_ * TD_ * H_];  // ctx partial sums (8 MB)

__device__ __forceinline__ float tanh_fast(float x) {
    float y;
    asm("tanh.approx.f32 %0, %1;" : "=f"(y) : "f"(x));
    return y;
}

// Packed fp32 pair FMA (Blackwell FFMA2): d = a*b + d, two lanes at once.
__device__ __forceinline__ void ffma2(unsigned long long& d,
                                      unsigned long long a,
                                      unsigned long long b) {
    asm("fma.rn.f32x2 %0, %1, %2, %0;" : "+l"(d) : "l"(a), "l"(b));
}
__device__ __forceinline__ unsigned long long rep2(float x) {
    unsigned long long p;
    asm("mov.b64 %0, {%1, %1};" : "=l"(p) : "r"(__float_as_uint(x)));
    return p;
}
__device__ __forceinline__ void unpk2(unsigned long long v,
                                      float& lo, float& hi) {
    unsigned a, b;
    asm("mov.b64 {%0, %1}, %2;" : "=r"(a), "=r"(b) : "l"(v));
    lo = __uint_as_float(a);
    hi = __uint_as_float(b);
}

// ---------------------------------------------------------------------------
// Projection GEMM, FFMA2 edition. (unchanged)
// BM=64, BN=32, BK=16, 128 threads. Blocks [0,512)=enc@Wa, [512,640)=dec@Ua.
// ---------------------------------------------------------------------------
__global__ __launch_bounds__(128) void proj_kernel(
    const float* __restrict__ enc, const float* __restrict__ dec,
    const float* __restrict__ Wa,  const float* __restrict__ Ua)
{
    __shared__ float As[16][68];
    __shared__ float Ws[16][36];

    const int bid = blockIdx.x;
    const float* __restrict__ A;
    const float* __restrict__ W;
    float* __restrict__ P;
    int bm, bn;
    if (bid < 512) {
        A = enc; W = Wa; P = g_ep;
        bm = (bid >> 3) * 64; bn = (bid & 7) * 32;
    } else {
        const int r = bid - 512;
        A = dec; W = Ua; P = g_dp;
        bm = (r >> 3) * 64; bn = (r & 7) * 32;
    }

    const int t  = threadIdx.x;
    const int tx = t & 15;
    const int ty = t >> 4;

    unsigned long long acc[4][2];
#pragma unroll
    for (int i = 0; i < 4; i++) { acc[i][0] = 0ull; acc[i][1] = 0ull; }

    const int rowA = t >> 2;
    const int kqA  = t & 3;
    const int kkW  = t >> 3;
    const int nqW  = t & 7;

    float4 a0 = *(const float4*)&A[(bm + rowA) * H_ + kqA * 4];
    float4 a1 = *(const float4*)&A[(bm + rowA + 32) * H_ + kqA * 4];
    float4 wv = *(const float4*)&W[kkW * H_ + bn + nqW * 4];

    for (int k0 = 0; k0 < H_; k0 += 16) {
        As[kqA * 4 + 0][rowA] = a0.x;
        As[kqA * 4 + 1][rowA] = a0.y;
        As[kqA * 4 + 2][rowA] = a0.z;
        As[kqA * 4 + 3][rowA] = a0.w;
        As[kqA * 4 + 0][rowA + 32] = a1.x;
        As[kqA * 4 + 1][rowA + 32] = a1.y;
        As[kqA * 4 + 2][rowA + 32] = a1.z;
        As[kqA * 4 + 3][rowA + 32] = a1.w;
        *(float4*)&Ws[kkW][nqW * 4] = wv;
        __syncthreads();

        if (k0 + 16 < H_) {
            a0 = *(const float4*)&A[(bm + rowA) * H_ + k0 + 16 + kqA * 4];
            a1 = *(const float4*)&A[(bm + rowA + 32) * H_ + k0 + 16 + kqA * 4];
            wv = *(const float4*)&W[(k0 + 16 + kkW) * H_ + bn + nqW * 4];
        }

#pragma unroll
        for (int k = 0; k < 16; k++) {
            ulonglong2 aP = *(const ulonglong2*)&As[k][ty * 8];
            ulonglong2 aQ = *(const ulonglong2*)&As[k][ty * 8 + 4];
            float2 bv = *(const float2*)&Ws[k][tx * 2];
            unsigned long long b0 = rep2(bv.x);
            unsigned long long b1 = rep2(bv.y);
            ffma2(acc[0][0], aP.x, b0);  ffma2(acc[0][1], aP.x, b1);
            ffma2(acc[1][0], aP.y, b0);  ffma2(acc[1][1], aP.y, b1);
            ffma2(acc[2][0], aQ.x, b0);  ffma2(acc[2][1], aQ.x, b1);
            ffma2(acc[3][0], aQ.y, b0);  ffma2(acc[3][1], aQ.y, b1);
        }
        __syncthreads();
    }

#pragma unroll
    for (int i2 = 0; i2 < 4; i2++) {
        float l0, h0f, l1, h1f;
        unpk2(acc[i2][0], l0, h0f);
        unpk2(acc[i2][1], l1, h1f);
        float2 r0 = {l0, l1};
        float2 r1 = {h0f, h1f};
        *(float2*)&P[(bm + ty * 8 + i2 * 2    ) * H_ + bn + tx * 2] = r0;
        *(float2*)&P[(bm + ty * 8 + i2 * 2 + 1) * H_ + bn + tx * 2] = r1;
    }
}

// ---------------------------------------------------------------------------
// Score kernel (unchanged, MUFU-bound at floor).
// ---------------------------------------------------------------------------
__global__ __launch_bounds__(256) void score_kernel(const float* __restrict__ V)
{
    __shared__ float sET[64][33];
    __shared__ float sdp[8][256];
    __shared__ float sV[256];

    const int t    = threadIdx.x;
    const int lane = t & 31;
    const int w    = t >> 5;
    const int b    = blockIdx.z;
    const int d0   = blockIdx.y * 8;
    const int e0   = blockIdx.x * 32;

    {
        const float4* dpsrc = (const float4*)(g_dp + (b * TD_ + d0) * H_);
        ((float4*)sdp)[t]       = dpsrc[t];
        ((float4*)sdp)[t + 256] = dpsrc[t + 256];
        if (t < 64) ((float4*)sV)[t] = ((const float4*)V)[t];
    }

    const float* ep = g_ep + b * TE_ * H_;
    float acc0 = 0.f, acc1 = 0.f;

    const int e_stg = t >> 3;
    const int hq    = t & 7;

    for (int ht = 0; ht < 4; ++ht) {
        __syncthreads();
        {
            const float* eprow = ep + (e0 + e_stg) * H_ + ht * 64;
            float4 v0 = *(const float4*)(eprow + hq * 4);
            float4 v1 = *(const float4*)(eprow + 32 + hq * 4);
            sET[hq * 4 + 0][e_stg] = v0.x;
            sET[hq * 4 + 1][e_stg] = v0.y;
            sET[hq * 4 + 2][e_stg] = v0.z;
            sET[hq * 4 + 3][e_stg] = v0.w;
            sET[32 + hq * 4 + 0][e_stg] = v1.x;
            sET[32 + hq * 4 + 1][e_stg] = v1.y;
            sET[32 + hq * 4 + 2][e_stg] = v1.z;
            sET[32 + hq * 4 + 3][e_stg] = v1.w;
        }
        __syncthreads();

        const float* dprow = &sdp[w][ht * 64];
        const float* vrow  = &sV[ht * 64];
#pragma unroll
        for (int h = 0; h < 64; h += 4) {
            float4 dv = *(const float4*)(dprow + h);
            float4 vv = *(const float4*)(vrow + h);
            acc0 += vv.x * tanh_fast(sET[h + 0][lane] + dv.x);
            acc1 += vv.y * tanh_fast(sET[h + 1][lane] + dv.y);
            acc0 += vv.z * tanh_fast(sET[h + 2][lane] + dv.z);
            acc1 += vv.w * tanh_fast(sET[h + 3][lane] + dv.w);
        }
    }

    g_score[(b * TD_ + d0 + w) * TE_ + e0 + lane] = acc0 + acc1;
}

// ---------------------------------------------------------------------------
// Softmax: normalizes g_score in place and writes the weights output.
// ---------------------------------------------------------------------------
__global__ __launch_bounds__(256) void softmax_kernel(float* __restrict__ out)
{
    const int t    = threadIdx.x;
    const int lane = t & 31;
    const int w    = t >> 5;
    const int row  = blockIdx.x * 8 + w;

    float4* srow = (float4*)(g_score + row * TE_);
    float4 v[4];
    float m = -1e30f;
#pragma unroll
    for (int i = 0; i < 4; i++) {
        v[i] = srow[lane + 32 * i];
        m = fmaxf(m, fmaxf(fmaxf(v[i].x, v[i].y), fmaxf(v[i].z, v[i].w)));
    }
#pragma unroll
    for (int o = 16; o > 0; o >>= 1)
        m = fmaxf(m, __shfl_xor_sync(0xffffffffu, m, o));
    float sum = 0.f;
#pragma unroll
    for (int i = 0; i < 4; i++) {
        v[i].x = __expf(v[i].x - m);
        v[i].y = __expf(v[i].y - m);
        v[i].z = __expf(v[i].z - m);
        v[i].w = __expf(v[i].w - m);
        sum += v[i].x + v[i].y + v[i].z + v[i].w;
    }
#pragma unroll
    for (int o = 16; o > 0; o >>= 1)
        sum += __shfl_xor_sync(0xffffffffu, sum, o);
    const float inv = __fdividef(1.f, sum);
    float4* gout = (float4*)(out + (size_t)B_ * TD_ * H_ + row * TE_);
#pragma unroll
    for (int i = 0; i < 4; i++) {
        v[i].x *= inv; v[i].y *= inv; v[i].z *= inv; v[i].w *= inv;
        srow[lane + 32 * i] = v[i];
        gout[lane + 32 * i] = v[i];
    }
}

// ---------------------------------------------------------------------------
// Context partials. Weights stored PRE-DUPLICATED in smem -> inner loop is
// pure LDS + FFMA2 (no register-pair duplication MOVs).
// Grid: ((H/64)*ESPLIT, TD/32, B) = (32, 4, 8) = 1024 blocks, 256 threads.
// Block tile: 32 d x 64 e x 64 h. 32 KB smem -> 7 blocks/SM.
// Warp w owns d rows {w, w+8, w+16, w+24}; lane owns h pair h0 + 2*lane.
// ---------------------------------------------------------------------------
__global__ __launch_bounds__(256) void ctx_part_kernel(
    const float* __restrict__ enc)
{
    __shared__ float sE[64][64];      // 16 KB: enc slab [e][h]
    __shared__ float sWd[32][128];    // 16 KB: duplicated weight pairs [d][2e]

    const int t    = threadIdx.x;
    const int lane = t & 31;
    const int w    = t >> 5;
    const int b    = blockIdx.z;
    const int d0   = blockIdx.y * 32;
    const int hq   = blockIdx.x & 3;        // h tile
    const int es   = blockIdx.x >> 2;       // e split (0..7)
    const int h0   = hq * 64;
    const int e0   = es * 64;

    const float* enc_b = enc + b * TE_ * H_;
    const float* wbase = g_score + (b * TD_ + d0) * TE_ + e0;

    // stage sE: 64 e-rows x 64 h  (1024 float4, 4 per thread)
#pragma unroll
    for (int i = 0; i < 4; i++) {
        int idx = t + i * 256;
        int row = idx >> 4, col = (idx & 15) * 4;
        *(float4*)&sE[row][col] =
            *(const float4*)&enc_b[(e0 + row) * H_ + h0 + col];
    }
    // stage sWd duplicated: 32 d-rows x 64 e -> (w,w) pairs.
    // thread t: row = t>>3, eq = t&7 -> 2 float4 loads -> 4 dup float4 stores
    {
        const int row = t >> 3;
        const int eq  = t & 7;           // 8 float4-groups of 8 e each? -> e base eq*8
#pragma unroll
        for (int g = 0; g < 2; g++) {
            float4 v = *(const float4*)&wbase[row * TE_ + eq * 8 + g * 4];
            float4 lo = {v.x, v.x, v.y, v.y};
            float4 hi = {v.z, v.z, v.w, v.w};
            *(float4*)&sWd[row][(eq * 8 + g * 4) * 2]     = lo;
            *(float4*)&sWd[row][(eq * 8 + g * 4) * 2 + 4] = hi;
        }
    }
    __syncthreads();

    unsigned long long acc0 = 0ull, acc1 = 0ull, acc2 = 0ull, acc3 = 0ull;

#pragma unroll 4
    for (int e2 = 0; e2 < 32; ++e2) {    // two e per iter
        ulonglong2 w0 = *(const ulonglong2*)&sWd[w     ][e2 * 4];
        ulonglong2 w1 = *(const ulonglong2*)&sWd[w +  8][e2 * 4];
        ulonglong2 w2 = *(const ulonglong2*)&sWd[w + 16][e2 * 4];
        ulonglong2 w3 = *(const ulonglong2*)&sWd[w + 24][e2 * 4];
        unsigned long long ev0 =
            *(const unsigned long long*)&sE[e2 * 2    ][lane * 2];
        unsigned long long ev1 =
            *(const unsigned long long*)&sE[e2 * 2 + 1][lane * 2];
        ffma2(acc0, w0.x, ev0);
        ffma2(acc1, w1.x, ev0);
        ffma2(acc2, w2.x, ev0);
        ffma2(acc3, w3.x, ev0);
        ffma2(acc0, w0.y, ev1);
        ffma2(acc1, w1.y, ev1);
        ffma2(acc2, w2.y, ev1);
        ffma2(acc3, w3.y, ev1);
    }

    float lo, hi;
    float2 o;
    unpk2(acc0, lo, hi); o.x = lo; o.y = hi;
    *(float2*)&g_part[es][(b * TD_ + d0 + w     ) * H_ + h0 + lane * 2] = o;
    unpk2(acc1, lo, hi); o.x = lo; o.y = hi;
    *(float2*)&g_part[es][(b * TD_ + d0 + w +  8) * H_ + h0 + lane * 2] = o;
    unpk2(acc2, lo, hi); o.x = lo; o.y = hi;
    *(float2*)&g_part[es][(b * TD_ + d0 + w + 16) * H_ + h0 + lane * 2] = o;
    unpk2(acc3, lo, hi); o.x = lo; o.y = hi;
    *(float2*)&g_part[es][(b * TD_ + d0 + w + 24) * H_ + h0 + lane * 2] = o;
}

// ---------------------------------------------------------------------------
// Combine: fixed-order tree over 8 partials (deterministic).
// 262144 floats = 65536 float4; grid 256 x 256 threads.
// ---------------------------------------------------------------------------
__global__ __launch_bounds__(256) void combine_kernel(float* __restrict__ out)
{
    const int i = blockIdx.x * 256 + threadIdx.x;   // float4 index
    float4 s[ESPLIT];
#pragma unroll
    for (int p = 0; p < ESPLIT; p++) s[p] = ((const float4*)g_part[p])[i];
    float4 o;
    o.x = ((s[0].x + s[1].x) + (s[2].x + s[3].x)) +
          ((s[4].x + s[5].x) + (s[6].x + s[7].x));
    o.y = ((s[0].y + s[1].y) + (s[2].y + s[3].y)) +
          ((s[4].y + s[5].y) + (s[6].y + s[7].y));
    o.z = ((s[0].z + s[1].z) + (s[2].z + s[3].z)) +
          ((s[4].z + s[5].z) + (s[6].z + s[7].z));
    o.w = ((s[0].w + s[1].w) + (s[2].w + s[3].w)) +
          ((s[4].w + s[5].w) + (s[6].w + s[7].w));
    ((float4*)out)[i] = o;
}

// ---------------------------------------------------------------------------
extern "C" void kernel_launch(void* const* d_in, const int* in_sizes, int n_in,
                              void* d_out, int out_size)
{
    const float* enc = (const float*)d_in[0];   // [B,TE,H]
    const float* dec = (const float*)d_in[1];   // [B,TD,H]
    const float* Wa  = (const float*)d_in[2];   // [H,H]
    const float* Ua  = (const float*)d_in[3];   // [H,H]
    const float* Va  = (const float*)d_in[4];   // [H,1]
    float* out = (float*)d_out;                 // context [B,TD,H] then weights [B,TD,TE]

    proj_kernel<<<dim3(640), 128>>>(enc, dec, Wa, Ua);
    score_kernel<<<dim3(TE_ / 32, TD_ / 8, B_), 256>>>(Va);
    softmax_kernel<<<dim3(128), 256>>>(out);
    ctx_part_kernel<<<dim3((H_ / 64) * ESPLIT, TD_ / 32, B_), 256>>>(enc);
    combine_kernel<<<dim3(256), 256>>>(out);
}

// round 8
// speedup vs baseline: 1.1231x; 1.1231x over previous
#include <cuda_runtime.h>

#define B_   8
#define TE_  512
#define TD_  128
#define H_   256
#define ESPLIT 4

// Scratch (allocation-free rule: device globals)
__device__ float g_ep[B_ * TE_ * H_];      // enc @ W_a   [B,TE,H]
__device__ float g_dp[B_ * TD_ * H_];      // dec @ U_a   [B,TD,H]
__device__ float g_score[B_ * TD_ * TE_];  // raw scores -> weights (in place)
__device__ float g_part[ESPLIT][B_ * TD_ * H_];  // ctx partial sums (4 MB)

__device__ __forceinline__ float tanh_fast(float x) {
    float y;
    asm("tanh.approx.f32 %0, %1;" : "=f"(y) : "f"(x));
    return y;
}

// Packed fp32 pair FMA (Blackwell FFMA2): d = a*b + d, two lanes at once.
__device__ __forceinline__ void ffma2(unsigned long long& d,
                                      unsigned long long a,
                                      unsigned long long b) {
    asm("fma.rn.f32x2 %0, %1, %2, %0;" : "+l"(d) : "l"(a), "l"(b));
}
__device__ __forceinline__ unsigned long long rep2(float x) {
    unsigned long long p;
    asm("mov.b64 %0, {%1, %1};" : "=l"(p) : "r"(__float_as_uint(x)));
    return p;
}
__device__ __forceinline__ void unpk2(unsigned long long v,
                                      float& lo, float& hi) {
    unsigned a, b;
    asm("mov.b64 {%0, %1}, %2;" : "=r"(a), "=r"(b) : "l"(v));
    lo = __uint_as_float(a);
    hi = __uint_as_float(b);
}

// ---------------------------------------------------------------------------
// Projection GEMM, FFMA2 edition. (unchanged)
// BM=64, BN=32, BK=16, 128 threads. Blocks [0,512)=enc@Wa, [512,640)=dec@Ua.
// ---------------------------------------------------------------------------
__global__ __launch_bounds__(128) void proj_kernel(
    const float* __restrict__ enc, const float* __restrict__ dec,
    const float* __restrict__ Wa,  const float* __restrict__ Ua)
{
    __shared__ float As[16][68];
    __shared__ float Ws[16][36];

    const int bid = blockIdx.x;
    const float* __restrict__ A;
    const float* __restrict__ W;
    float* __restrict__ P;
    int bm, bn;
    if (bid < 512) {
        A = enc; W = Wa; P = g_ep;
        bm = (bid >> 3) * 64; bn = (bid & 7) * 32;
    } else {
        const int r = bid - 512;
        A = dec; W = Ua; P = g_dp;
        bm = (r >> 3) * 64; bn = (r & 7) * 32;
    }

    const int t  = threadIdx.x;
    const int tx = t & 15;
    const int ty = t >> 4;

    unsigned long long acc[4][2];
#pragma unroll
    for (int i = 0; i < 4; i++) { acc[i][0] = 0ull; acc[i][1] = 0ull; }

    const int rowA = t >> 2;
    const int kqA  = t & 3;
    const int kkW  = t >> 3;
    const int nqW  = t & 7;

    float4 a0 = *(const float4*)&A[(bm + rowA) * H_ + kqA * 4];
    float4 a1 = *(const float4*)&A[(bm + rowA + 32) * H_ + kqA * 4];
    float4 wv = *(const float4*)&W[kkW * H_ + bn + nqW * 4];

    for (int k0 = 0; k0 < H_; k0 += 16) {
        As[kqA * 4 + 0][rowA] = a0.x;
        As[kqA * 4 + 1][rowA] = a0.y;
        As[kqA * 4 + 2][rowA] = a0.z;
        As[kqA * 4 + 3][rowA] = a0.w;
        As[kqA * 4 + 0][rowA + 32] = a1.x;
        As[kqA * 4 + 1][rowA + 32] = a1.y;
        As[kqA * 4 + 2][rowA + 32] = a1.z;
        As[kqA * 4 + 3][rowA + 32] = a1.w;
        *(float4*)&Ws[kkW][nqW * 4] = wv;
        __syncthreads();

        if (k0 + 16 < H_) {
            a0 = *(const float4*)&A[(bm + rowA) * H_ + k0 + 16 + kqA * 4];
            a1 = *(const float4*)&A[(bm + rowA + 32) * H_ + k0 + 16 + kqA * 4];
            wv = *(const float4*)&W[(k0 + 16 + kkW) * H_ + bn + nqW * 4];
        }

#pragma unroll
        for (int k = 0; k < 16; k++) {
            ulonglong2 aP = *(const ulonglong2*)&As[k][ty * 8];
            ulonglong2 aQ = *(const ulonglong2*)&As[k][ty * 8 + 4];
            float2 bv = *(const float2*)&Ws[k][tx * 2];
            unsigned long long b0 = rep2(bv.x);
            unsigned long long b1 = rep2(bv.y);
            ffma2(acc[0][0], aP.x, b0);  ffma2(acc[0][1], aP.x, b1);
            ffma2(acc[1][0], aP.y, b0);  ffma2(acc[1][1], aP.y, b1);
            ffma2(acc[2][0], aQ.x, b0);  ffma2(acc[2][1], aQ.x, b1);
            ffma2(acc[3][0], aQ.y, b0);  ffma2(acc[3][1], aQ.y, b1);
        }
        __syncthreads();
    }

#pragma unroll
    for (int i2 = 0; i2 < 4; i2++) {
        float l0, h0f, l1, h1f;
        unpk2(acc[i2][0], l0, h0f);
        unpk2(acc[i2][1], l1, h1f);
        float2 r0 = {l0, l1};
        float2 r1 = {h0f, h1f};
        *(float2*)&P[(bm + ty * 8 + i2 * 2    ) * H_ + bn + tx * 2] = r0;
        *(float2*)&P[(bm + ty * 8 + i2 * 2 + 1) * H_ + bn + tx * 2] = r1;
    }
}

// ---------------------------------------------------------------------------
// Score kernel (unchanged, MUFU-bound at floor).
// ---------------------------------------------------------------------------
__global__ __launch_bounds__(256) void score_kernel(const float* __restrict__ V)
{
    __shared__ float sET[64][33];
    __shared__ float sdp[8][256];
    __shared__ float sV[256];

    const int t    = threadIdx.x;
    const int lane = t & 31;
    const int w    = t >> 5;
    const int b    = blockIdx.z;
    const int d0   = blockIdx.y * 8;
    const int e0   = blockIdx.x * 32;

    {
        const float4* dpsrc = (const float4*)(g_dp + (b * TD_ + d0) * H_);
        ((float4*)sdp)[t]       = dpsrc[t];
        ((float4*)sdp)[t + 256] = dpsrc[t + 256];
        if (t < 64) ((float4*)sV)[t] = ((const float4*)V)[t];
    }

    const float* ep = g_ep + b * TE_ * H_;
    float acc0 = 0.f, acc1 = 0.f;

    const int e_stg = t >> 3;
    const int hq    = t & 7;

    for (int ht = 0; ht < 4; ++ht) {
        __syncthreads();
        {
            const float* eprow = ep + (e0 + e_stg) * H_ + ht * 64;
            float4 v0 = *(const float4*)(eprow + hq * 4);
            float4 v1 = *(const float4*)(eprow + 32 + hq * 4);
            sET[hq * 4 + 0][e_stg] = v0.x;
            sET[hq * 4 + 1][e_stg] = v0.y;
            sET[hq * 4 + 2][e_stg] = v0.z;
            sET[hq * 4 + 3][e_stg] = v0.w;
            sET[32 + hq * 4 + 0][e_stg] = v1.x;
            sET[32 + hq * 4 + 1][e_stg] = v1.y;
            sET[32 + hq * 4 + 2][e_stg] = v1.z;
            sET[32 + hq * 4 + 3][e_stg] = v1.w;
        }
        __syncthreads();

        const float* dprow = &sdp[w][ht * 64];
        const float* vrow  = &sV[ht * 64];
#pragma unroll
        for (int h = 0; h < 64; h += 4) {
            float4 dv = *(const float4*)(dprow + h);
            float4 vv = *(const float4*)(vrow + h);
            acc0 += vv.x * tanh_fast(sET[h + 0][lane] + dv.x);
            acc1 += vv.y * tanh_fast(sET[h + 1][lane] + dv.y);
            acc0 += vv.z * tanh_fast(sET[h + 2][lane] + dv.z);
            acc1 += vv.w * tanh_fast(sET[h + 3][lane] + dv.w);
        }
    }

    g_score[(b * TD_ + d0 + w) * TE_ + e0 + lane] = acc0 + acc1;
}

// ---------------------------------------------------------------------------
// Softmax: normalizes g_score in place and writes the weights output.
// Grid: 256 blocks x 4 warps = 1024 rows.
// ---------------------------------------------------------------------------
__global__ __launch_bounds__(128) void softmax_kernel(float* __restrict__ out)
{
    const int t    = threadIdx.x;
    const int lane = t & 31;
    const int w    = t >> 5;
    const int row  = blockIdx.x * 4 + w;

    float4* srow = (float4*)(g_score + row * TE_);
    float4 v[4];
    float m = -1e30f;
#pragma unroll
    for (int i = 0; i < 4; i++) {
        v[i] = srow[lane + 32 * i];
        m = fmaxf(m, fmaxf(fmaxf(v[i].x, v[i].y), fmaxf(v[i].z, v[i].w)));
    }
#pragma unroll
    for (int o = 16; o > 0; o >>= 1)
        m = fmaxf(m, __shfl_xor_sync(0xffffffffu, m, o));
    float sum = 0.f;
#pragma unroll
    for (int i = 0; i < 4; i++) {
        v[i].x = __expf(v[i].x - m);
        v[i].y = __expf(v[i].y - m);
        v[i].z = __expf(v[i].z - m);
        v[i].w = __expf(v[i].w - m);
        sum += v[i].x + v[i].y + v[i].z + v[i].w;
    }
#pragma unroll
    for (int o = 16; o > 0; o >>= 1)
        sum += __shfl_xor_sync(0xffffffffu, sum, o);
    const float inv = __fdividef(1.f, sum);
    float4* gout = (float4*)(out + (size_t)B_ * TD_ * H_ + row * TE_);
#pragma unroll
    for (int i = 0; i < 4; i++) {
        v[i].x *= inv; v[i].y *= inv; v[i].z *= inv; v[i].w *= inv;
        srow[lane + 32 * i] = v[i];
        gout[lane + 32 * i] = v[i];
    }
}

// ---------------------------------------------------------------------------
// Context partials, d-packed FFMA2 edition.
// acc[(d,d+1), h] += (w[d,e], w[d+1,e]) * dup(enc[e,h])
// Weights staged TRANSPOSED sWt[e][d] (d contiguous) -> packed pairs load
// directly as warp-uniform broadcast LDS.128; one rep2 per (e, thread)
// amortized over 4 FFMA2.
// Grid: ((H/64)*ESPLIT, TD/32, B) = (16, 4, 8) = 512 blocks, 256 threads.
// Block tile: 32 d x 128 e x 64 h. 48 KB static smem -> 4 blocks/SM.
// Thread t: dg = t>>6 (8 d-rows dg*8..dg*8+7), h_idx = t&63.
// ---------------------------------------------------------------------------
__global__ __launch_bounds__(256) void ctx_part_kernel(
    const float* __restrict__ enc)
{
    __shared__ float sE[128][64];    // 32 KB: enc slab [e][h]
    __shared__ float sWt[128][32];   // 16 KB: weights transposed [e][d]

    const int t     = threadIdx.x;
    const int dg    = t >> 6;               // 0..3, uniform within warp
    const int h_idx = t & 63;               // consecutive within warp
    const int b     = blockIdx.z;
    const int d0    = blockIdx.y * 32;
    const int hq    = blockIdx.x & 3;       // h tile
    const int es    = blockIdx.x >> 2;      // e split (0..3)
    const int h0    = hq * 64;
    const int e0    = es * 128;

    const float* enc_b = enc + b * TE_ * H_;
    const float* wbase = g_score + (b * TD_ + d0) * TE_ + e0;

    // stage sE: 128 e-rows x 64 h (2048 float4, 8 per thread), coalesced
#pragma unroll
    for (int i = 0; i < 8; i++) {
        int idx = t + i * 256;
        int row = idx >> 4, col = (idx & 15) * 4;
        *(float4*)&sE[row][col] =
            *(const float4*)&enc_b[(e0 + row) * H_ + h0 + col];
    }
    // stage sWt transposed: d-fast so smem writes are conflict-free.
    // idx: d = idx&31 (consecutive in warp), e4 = idx>>5. L2-resident reads.
#pragma unroll
    for (int i = 0; i < 4; i++) {
        int idx = t + i * 256;              // 0..1023
        int d = idx & 31, e4 = idx >> 5;
        float4 v = *(const float4*)&wbase[d * TE_ + e4 * 4];
        sWt[e4 * 4 + 0][d] = v.x;
        sWt[e4 * 4 + 1][d] = v.y;
        sWt[e4 * 4 + 2][d] = v.z;
        sWt[e4 * 4 + 3][d] = v.w;
    }
    __syncthreads();

    unsigned long long acc0 = 0ull, acc1 = 0ull, acc2 = 0ull, acc3 = 0ull;

#pragma unroll 4
    for (int e = 0; e < 128; ++e) {
        unsigned long long ev = rep2(sE[e][h_idx]);
        ulonglong2 wp0 = *(const ulonglong2*)&sWt[e][dg * 8];      // (d0,d1),(d2,d3)
        ulonglong2 wp1 = *(const ulonglong2*)&sWt[e][dg * 8 + 4];  // (d4,d5),(d6,d7)
        ffma2(acc0, wp0.x, ev);
        ffma2(acc1, wp0.y, ev);
        ffma2(acc2, wp1.x, ev);
        ffma2(acc3, wp1.y, ev);
    }

    float* pbase = g_part[es] + (b * TD_ + d0 + dg * 8) * H_ + h0 + h_idx;
    float lo, hi;
    unpk2(acc0, lo, hi);
    pbase[0 * H_] = lo;  pbase[1 * H_] = hi;
    unpk2(acc1, lo, hi);
    pbase[2 * H_] = lo;  pbase[3 * H_] = hi;
    unpk2(acc2, lo, hi);
    pbase[4 * H_] = lo;  pbase[5 * H_] = hi;
    unpk2(acc3, lo, hi);
    pbase[6 * H_] = lo;  pbase[7 * H_] = hi;
}

// ---------------------------------------------------------------------------
// Combine: out = (p0+p1)+(p2+p3), fixed order (deterministic).
// 262144 floats = 65536 float4; grid 256 x 256 threads.
// ---------------------------------------------------------------------------
__global__ __launch_bounds__(256) void combine_kernel(float* __restrict__ out)
{
    const int i = blockIdx.x * 256 + threadIdx.x;   // float4 index
    const float4 p0 = ((const float4*)g_part[0])[i];
    const float4 p1 = ((const float4*)g_part[1])[i];
    const float4 p2 = ((const float4*)g_part[2])[i];
    const float4 p3 = ((const float4*)g_part[3])[i];
    float4 o;
    o.x = (p0.x + p1.x) + (p2.x + p3.x);
    o.y = (p0.y + p1.y) + (p2.y + p3.y);
    o.z = (p0.z + p1.z) + (p2.z + p3.z);
    o.w = (p0.w + p1.w) + (p2.w + p3.w);
    ((float4*)out)[i] = o;
}

// ---------------------------------------------------------------------------
extern "C" void kernel_launch(void* const* d_in, const int* in_sizes, int n_in,
                              void* d_out, int out_size)
{
    const float* enc = (const float*)d_in[0];   // [B,TE,H]
    const float* dec = (const float*)d_in[1];   // [B,TD,H]
    const float* Wa  = (const float*)d_in[2];   // [H,H]
    const float* Ua  = (const float*)d_in[3];   // [H,H]
    const float* Va  = (const float*)d_in[4];   // [H,1]
    float* out = (float*)d_out;                 // context [B,TD,H] then weights [B,TD,TE]

    proj_kernel<<<dim3(640), 128>>>(enc, dec, Wa, Ua);
    score_kernel<<<dim3(TE_ / 32, TD_ / 8, B_), 256>>>(Va);
    softmax_kernel<<<dim3(256), 128>>>(out);
    ctx_part_kernel<<<dim3((H_ / 64) * ESPLIT, TD_ / 32, B_), 256>>>(enc);
    combine_kernel<<<dim3(256), 256>>>(out);
}

// round 9
// speedup vs baseline: 1.2423x; 1.1061x over previous
#include <cuda_runtime.h>
#include <cuda_fp16.h>

#define B_   8
#define TE_  512
#define TD_  128
#define H_   256
#define ESPLIT 4

// Scratch (allocation-free rule: device globals)
__device__ float g_ep[B_ * TE_ * H_];      // enc @ W_a   [B,TE,H]
__device__ float g_dp[B_ * TD_ * H_];      // dec @ U_a   [B,TD,H]
__device__ float g_score[B_ * TD_ * TE_];  // raw scores -> weights (in place)
__device__ float g_part[ESPLIT][B_ * TD_ * H_];  // ctx partial sums (4 MB)

__device__ __forceinline__ unsigned tanh2_fast(unsigned x2) {
    unsigned y2;
    asm("tanh.approx.f16x2 %0, %1;" : "=r"(y2) : "r"(x2));
    return y2;
}

// Packed fp32 pair FMA (Blackwell FFMA2): d = a*b + d, two lanes at once.
__device__ __forceinline__ void ffma2(unsigned long long& d,
                                      unsigned long long a,
                                      unsigned long long b) {
    asm("fma.rn.f32x2 %0, %1, %2, %0;" : "+l"(d) : "l"(a), "l"(b));
}
__device__ __forceinline__ unsigned long long rep2(float x) {
    unsigned long long p;
    asm("mov.b64 %0, {%1, %1};" : "=l"(p) : "r"(__float_as_uint(x)));
    return p;
}
__device__ __forceinline__ unsigned long long pk2(float lo, float hi) {
    unsigned long long p;
    asm("mov.b64 %0, {%1, %2};" : "=l"(p)
        : "r"(__float_as_uint(lo)), "r"(__float_as_uint(hi)));
    return p;
}
__device__ __forceinline__ void unpk2(unsigned long long v,
                                      float& lo, float& hi) {
    unsigned a, b;
    asm("mov.b64 {%0, %1}, %2;" : "=r"(a), "=r"(b) : "l"(v));
    lo = __uint_as_float(a);
    hi = __uint_as_float(b);
}
__device__ __forceinline__ unsigned packh2(float a, float b) {
    __half2 h = __floats2half2_rn(a, b);   // lo = a, hi = b
    return *(unsigned*)&h;
}

// ---------------------------------------------------------------------------
// Projection GEMM, FFMA2 edition. (unchanged)
// BM=64, BN=32, BK=16, 128 threads. Blocks [0,512)=enc@Wa, [512,640)=dec@Ua.
// ---------------------------------------------------------------------------
__global__ __launch_bounds__(128) void proj_kernel(
    const float* __restrict__ enc, const float* __restrict__ dec,
    const float* __restrict__ Wa,  const float* __restrict__ Ua)
{
    __shared__ float As[16][68];
    __shared__ float Ws[16][36];

    const int bid = blockIdx.x;
    const float* __restrict__ A;
    const float* __restrict__ W;
    float* __restrict__ P;
    int bm, bn;
    if (bid < 512) {
        A = enc; W = Wa; P = g_ep;
        bm = (bid >> 3) * 64; bn = (bid & 7) * 32;
    } else {
        const int r = bid - 512;
        A = dec; W = Ua; P = g_dp;
        bm = (r >> 3) * 64; bn = (r & 7) * 32;
    }

    const int t  = threadIdx.x;
    const int tx = t & 15;
    const int ty = t >> 4;

    unsigned long long acc[4][2];
#pragma unroll
    for (int i = 0; i < 4; i++) { acc[i][0] = 0ull; acc[i][1] = 0ull; }

    const int rowA = t >> 2;
    const int kqA  = t & 3;
    const int kkW  = t >> 3;
    const int nqW  = t & 7;

    float4 a0 = *(const float4*)&A[(bm + rowA) * H_ + kqA * 4];
    float4 a1 = *(const float4*)&A[(bm + rowA + 32) * H_ + kqA * 4];
    float4 wv = *(const float4*)&W[kkW * H_ + bn + nqW * 4];

    for (int k0 = 0; k0 < H_; k0 += 16) {
        As[kqA * 4 + 0][rowA] = a0.x;
        As[kqA * 4 + 1][rowA] = a0.y;
        As[kqA * 4 + 2][rowA] = a0.z;
        As[kqA * 4 + 3][rowA] = a0.w;
        As[kqA * 4 + 0][rowA + 32] = a1.x;
        As[kqA * 4 + 1][rowA + 32] = a1.y;
        As[kqA * 4 + 2][rowA + 32] = a1.z;
        As[kqA * 4 + 3][rowA + 32] = a1.w;
        *(float4*)&Ws[kkW][nqW * 4] = wv;
        __syncthreads();

        if (k0 + 16 < H_) {
            a0 = *(const float4*)&A[(bm + rowA) * H_ + k0 + 16 + kqA * 4];
            a1 = *(const float4*)&A[(bm + rowA + 32) * H_ + k0 + 16 + kqA * 4];
            wv = *(const float4*)&W[(k0 + 16 + kkW) * H_ + bn + nqW * 4];
        }

#pragma unroll
        for (int k = 0; k < 16; k++) {
            ulonglong2 aP = *(const ulonglong2*)&As[k][ty * 8];
            ulonglong2 aQ = *(const ulonglong2*)&As[k][ty * 8 + 4];
            float2 bv = *(const float2*)&Ws[k][tx * 2];
            unsigned long long b0 = rep2(bv.x);
            unsigned long long b1 = rep2(bv.y);
            ffma2(acc[0][0], aP.x, b0);  ffma2(acc[0][1], aP.x, b1);
            ffma2(acc[1][0], aP.y, b0);  ffma2(acc[1][1], aP.y, b1);
            ffma2(acc[2][0], aQ.x, b0);  ffma2(acc[2][1], aQ.x, b1);
            ffma2(acc[3][0], aQ.y, b0);  ffma2(acc[3][1], aQ.y, b1);
        }
        __syncthreads();
    }

#pragma unroll
    for (int i2 = 0; i2 < 4; i2++) {
        float l0, h0f, l1, h1f;
        unpk2(acc[i2][0], l0, h0f);
        unpk2(acc[i2][1], l1, h1f);
        float2 r0 = {l0, l1};
        float2 r1 = {h0f, h1f};
        *(float2*)&P[(bm + ty * 8 + i2 * 2    ) * H_ + bn + tx * 2] = r0;
        *(float2*)&P[(bm + ty * 8 + i2 * 2 + 1) * H_ + bn + tx * 2] = r1;
    }
}

// ---------------------------------------------------------------------------
// Score kernel, f16x2 tanh edition: one MUFU per TWO h-channels.
// ep/dp staged as packed f16x2 h-pairs; V kept as f32x2 pairs for FFMA2.
// Grid: (TE/32, TD/8, B) = 2048 blocks, 256 threads.
// Warp w owns decoder row d0+w; lane owns encoder row e0+lane.
// ---------------------------------------------------------------------------
__global__ __launch_bounds__(256) void score_kernel(const float* __restrict__ V)
{
    __shared__ unsigned sET2[32][33];            // 4.2 KB: [h-pair][e] f16x2
    __shared__ unsigned sdp2[8][128];            // 4 KB: dp rows as f16x2
    __shared__ unsigned long long sVp[128];      // 1 KB: V as f32x2 pairs

    const int t    = threadIdx.x;
    const int lane = t & 31;
    const int w    = t >> 5;
    const int b    = blockIdx.z;
    const int d0   = blockIdx.y * 8;
    const int e0   = blockIdx.x * 32;

    // Stage dp (8 rows x 256 -> f16x2) and V pairs once.
    {
        const float4* dpsrc = (const float4*)(g_dp + (b * TD_ + d0) * H_);
#pragma unroll
        for (int i = 0; i < 2; i++) {
            int idx = t + i * 256;               // 0..511 float4 slots
            int row = idx >> 6, colq = idx & 63;
            float4 v = dpsrc[row * 64 + colq];
            sdp2[row][colq * 2]     = packh2(v.x, v.y);
            sdp2[row][colq * 2 + 1] = packh2(v.z, v.w);
        }
        if (t < 128) {
            float2 vv = ((const float2*)V)[t];
            sVp[t] = pk2(vv.x, vv.y);
        }
    }

    const float* ep = g_ep + b * TE_ * H_;
    unsigned long long acc = 0ull;               // f32x2: even/odd h partials

    for (int ht = 0; ht < 4; ++ht) {
        __syncthreads();                         // covers dp/V staging on iter 0
        // Stage sET2: 32 e-rows x 64 h -> 32 h-pairs x 32 e (transposed)
#pragma unroll
        for (int i = 0; i < 2; i++) {
            int idx = t + i * 256;               // 0..511
            int e_row = idx >> 4, hq = idx & 15;
            float4 v = *(const float4*)&ep[(e0 + e_row) * H_ + ht * 64 + hq * 4];
            sET2[hq * 2    ][e_row] = packh2(v.x, v.y);
            sET2[hq * 2 + 1][e_row] = packh2(v.z, v.w);
        }
        __syncthreads();

        const unsigned* dprow = &sdp2[w][ht * 32];
        const unsigned long long* vrow = &sVp[ht * 32];
#pragma unroll
        for (int hp = 0; hp < 32; ++hp) {
            unsigned ep2 = sET2[hp][lane];
            unsigned dp2 = dprow[hp];
            __half2 arg = __hadd2(*(__half2*)&ep2, *(__half2*)&dp2);
            unsigned t2 = tanh2_fast(*(unsigned*)&arg);
            __half2 th = *(__half2*)&t2;
            float lo = __low2float(th);
            float hi = __high2float(th);
            ffma2(acc, vrow[hp], pk2(lo, hi));
        }
    }

    float slo, shi;
    unpk2(acc, slo, shi);
    g_score[(b * TD_ + d0 + w) * TE_ + e0 + lane] = slo + shi;
}

// ---------------------------------------------------------------------------
// Softmax: normalizes g_score in place and writes the weights output.
// Grid: 128 blocks x 8 warps = 1024 rows.
// ---------------------------------------------------------------------------
__global__ __launch_bounds__(256) void softmax_kernel(float* __restrict__ out)
{
    const int t    = threadIdx.x;
    const int lane = t & 31;
    const int w    = t >> 5;
    const int row  = blockIdx.x * 8 + w;

    float4* srow = (float4*)(g_score + row * TE_);
    float4 v[4];
    float m = -1e30f;
#pragma unroll
    for (int i = 0; i < 4; i++) {
        v[i] = srow[lane + 32 * i];
        m = fmaxf(m, fmaxf(fmaxf(v[i].x, v[i].y), fmaxf(v[i].z, v[i].w)));
    }
#pragma unroll
    for (int o = 16; o > 0; o >>= 1)
        m = fmaxf(m, __shfl_xor_sync(0xffffffffu, m, o));
    float sum = 0.f;
#pragma unroll
    for (int i = 0; i < 4; i++) {
        v[i].x = __expf(v[i].x - m);
        v[i].y = __expf(v[i].y - m);
        v[i].z = __expf(v[i].z - m);
        v[i].w = __expf(v[i].w - m);
        sum += v[i].x + v[i].y + v[i].z + v[i].w;
    }
#pragma unroll
    for (int o = 16; o > 0; o >>= 1)
        sum += __shfl_xor_sync(0xffffffffu, sum, o);
    const float inv = __fdividef(1.f, sum);
    float4* gout = (float4*)(out + (size_t)B_ * TD_ * H_ + row * TE_);
#pragma unroll
    for (int i = 0; i < 4; i++) {
        v[i].x *= inv; v[i].y *= inv; v[i].z *= inv; v[i].w *= inv;
        srow[lane + 32 * i] = v[i];
        gout[lane + 32 * i] = v[i];
    }
}

// ---------------------------------------------------------------------------
// Context partials (reverted to the empirically-best R6 version, 14.1us).
// Grid: ((H/64)*ESPLIT, TD/32, B) = (16, 4, 8) = 512 blocks, 256 threads.
// Block tile: 32 d x 128 e x 64 h. 48 KB smem.
// Warp w owns d rows {w, w+8, w+16, w+24}; lane owns h pair h0 + 2*lane.
// ---------------------------------------------------------------------------
__global__ __launch_bounds__(256) void ctx_part_kernel(
    const float* __restrict__ enc)
{
    __shared__ float sE[128][64];    // 32 KB: enc slab [e][h]
    __shared__ float sWt[32][128];   // 16 KB: weights slab [d][e]

    const int t    = threadIdx.x;
    const int lane = t & 31;
    const int w    = t >> 5;
    const int b    = blockIdx.z;
    const int d0   = blockIdx.y * 32;
    const int hq   = blockIdx.x & 3;        // h tile
    const int es   = blockIdx.x >> 2;       // e split (0..3)
    const int h0   = hq * 64;
    const int e0   = es * 128;

    const float* enc_b = enc + b * TE_ * H_;
    const float* wbase = g_score + (b * TD_ + d0) * TE_;

    // stage sE: 128 e-rows x 64 h
#pragma unroll
    for (int i = 0; i < 8; i++) {
        int idx = t + i * 256;               // 2048 float4 slots
        int row = idx >> 4, col = (idx & 15) * 4;
        *(float4*)&sE[row][col] =
            *(const float4*)&enc_b[(e0 + row) * H_ + h0 + col];
    }
    // stage sWt: 32 d-rows x 128 e
#pragma unroll
    for (int i = 0; i < 4; i++) {
        int idx = t + i * 256;               // 1024 float4 slots
        int row = idx >> 5, col = (idx & 31) * 4;
        *(float4*)&sWt[row][col] =
            *(const float4*)&wbase[row * TE_ + e0 + col];
    }
    __syncthreads();

    unsigned long long acc[4] = {0ull, 0ull, 0ull, 0ull};

#pragma unroll 2
    for (int e4 = 0; e4 < 32; ++e4) {
        float4 wr0 = *(const float4*)&sWt[w     ][e4 * 4];
        float4 wr1 = *(const float4*)&sWt[w +  8][e4 * 4];
        float4 wr2 = *(const float4*)&sWt[w + 16][e4 * 4];
        float4 wr3 = *(const float4*)&sWt[w + 24][e4 * 4];
        const float* f0 = (const float*)&wr0;
        const float* f1 = (const float*)&wr1;
        const float* f2 = (const float*)&wr2;
        const float* f3 = (const float*)&wr3;
#pragma unroll
        for (int j = 0; j < 4; j++) {
            unsigned long long ev =
                *(const unsigned long long*)&sE[e4 * 4 + j][lane * 2];
            ffma2(acc[0], rep2(f0[j]), ev);
            ffma2(acc[1], rep2(f1[j]), ev);
            ffma2(acc[2], rep2(f2[j]), ev);
            ffma2(acc[3], rep2(f3[j]), ev);
        }
    }

#pragma unroll
    for (int r = 0; r < 4; r++) {
        float lo, hi;
        unpk2(acc[r], lo, hi);
        float2 o = {lo, hi};
        *(float2*)&g_part[es][(b * TD_ + d0 + w + 8 * r) * H_ + h0 + lane * 2] = o;
    }
}

// ---------------------------------------------------------------------------
// Combine: out = (p0+p1)+(p2+p3), fixed order (deterministic).
// 262144 floats = 65536 float4; grid 256 x 256 threads.
// ---------------------------------------------------------------------------
__global__ __launch_bounds__(256) void combine_kernel(float* __restrict__ out)
{
    const int i = blockIdx.x * 256 + threadIdx.x;   // float4 index
    const float4 p0 = ((const float4*)g_part[0])[i];
    const float4 p1 = ((const float4*)g_part[1])[i];
    const float4 p2 = ((const float4*)g_part[2])[i];
    const float4 p3 = ((const float4*)g_part[3])[i];
    float4 o;
    o.x = (p0.x + p1.x) + (p2.x + p3.x);
    o.y = (p0.y + p1.y) + (p2.y + p3.y);
    o.z = (p0.z + p1.z) + (p2.z + p3.z);
    o.w = (p0.w + p1.w) + (p2.w + p3.w);
    ((float4*)out)[i] = o;
}

// ---------------------------------------------------------------------------
extern "C" void kernel_launch(void* const* d_in, const int* in_sizes, int n_in,
                              void* d_out, int out_size)
{
    const float* enc = (const float*)d_in[0];   // [B,TE,H]
    const float* dec = (const float*)d_in[1];   // [B,TD,H]
    const float* Wa  = (const float*)d_in[2];   // [H,H]
    const float* Ua  = (const float*)d_in[3];   // [H,H]
    const float* Va  = (const float*)d_in[4];   // [H,1]
    float* out = (float*)d_out;                 // context [B,TD,H] then weights [B,TD,TE]

    proj_kernel<<<dim3(640), 128>>>(enc, dec, Wa, Ua);
    score_kernel<<<dim3(TE_ / 32, TD_ / 8, B_), 256>>>(Va);
    softmax_kernel<<<dim3(128), 256>>>(out);
    ctx_part_kernel<<<dim3((H_ / 64) * ESPLIT, TD_ / 32, B_), 256>>>(enc);
    combine_kernel<<<dim3(256), 256>>>(out);
}